// round 11
// baseline (speedup 1.0000x reference)
#include <cuda_runtime.h>
#include <cuda_bf16.h>
#include <cstdint>

#define HIDDEN   160
#define IN_DIM   784
#define NLAYERS  32
#define NCLASSES 10
#define BM       128
#define NTH      256
#define LDA      168              // padded row length (bf16), 336B stride
#define STRB     (LDA * 2)

// W half-layer chunk: 80 k-rows x 168 cols, hi plane then lo plane
#define WCH_PLANE  26880          // 80*168*2 bytes
#define WCHUNK     53760          // hi+lo
#define NCHUNK     (NLAYERS * 2)  // 64

// SMEM layout
#define A_HI   0
#define A_LO   43008              // 128*336
#define WB0    86016
#define WB1    139776             // WB0 + WCHUNK (contiguous pair)
#define SM_TOTAL 193536

// pre-split weights, chunk-ordered
// layer chunks: ch = 2*l + c, each WCHUNK bytes: [hi 80x168][lo 80x168]
__device__ __align__(16) __nv_bfloat16 g_lw[NCHUNK * 2 * 80 * LDA];
// embed chunks: 10 chunks of 80 k-rows (k padded to 800), same per-chunk layout
__device__ __align__(16) __nv_bfloat16 g_ew[10 * 2 * 80 * LDA];

__device__ __forceinline__ uint32_t smem_u32(const void* p) {
    uint32_t a;
    asm("{ .reg .u64 t; cvta.to.shared.u64 t, %1; cvt.u32.u64 %0, t; }"
        : "=r"(a) : "l"(p));
    return a;
}

__device__ __forceinline__ void ldsm_x4(uint32_t (&r)[4], uint32_t addr) {
    asm volatile("ldmatrix.sync.aligned.m8n8.x4.shared.b16 {%0,%1,%2,%3}, [%4];"
        : "=r"(r[0]), "=r"(r[1]), "=r"(r[2]), "=r"(r[3]) : "r"(addr));
}

__device__ __forceinline__ void ldsm_x4t(uint32_t (&r)[4], uint32_t addr) {
    asm volatile("ldmatrix.sync.aligned.m8n8.x4.trans.shared.b16 {%0,%1,%2,%3}, [%4];"
        : "=r"(r[0]), "=r"(r[1]), "=r"(r[2]), "=r"(r[3]) : "r"(addr));
}

__device__ __forceinline__ void mma_bf16(float (&d)[4], const uint32_t* a,
                                         uint32_t b0, uint32_t b1) {
    asm volatile(
        "mma.sync.aligned.m16n8k16.row.col.f32.bf16.bf16.f32 "
        "{%0,%1,%2,%3}, {%4,%5,%6,%7}, {%8,%9}, {%0,%1,%2,%3};"
        : "+f"(d[0]), "+f"(d[1]), "+f"(d[2]), "+f"(d[3])
        : "r"(a[0]), "r"(a[1]), "r"(a[2]), "r"(a[3]), "r"(b0), "r"(b1));
}

__device__ __forceinline__ void cp16(uint32_t dst, const void* src) {
    asm volatile("cp.async.cg.shared.global [%0], [%1], 16;"
                 :: "r"(dst), "l"(src) : "memory");
}
#define CP_COMMIT() asm volatile("cp.async.commit_group;" ::: "memory")
#define CP_WAIT(n)  asm volatile("cp.async.wait_group %0;" :: "n"(n) : "memory")

__device__ __forceinline__ void split_store(char* smem, int off_hi, int off_lo,
                                            float v0, float v1) {
    __nv_bfloat16 h0 = __float2bfloat16(v0);
    __nv_bfloat16 h1 = __float2bfloat16(v1);
    float l0 = v0 - __bfloat162float(h0);
    float l1 = v1 - __bfloat162float(h1);
    __nv_bfloat162 hp = __halves2bfloat162(h0, h1);
    __nv_bfloat162 lp = __halves2bfloat162(__float2bfloat16(l0), __float2bfloat16(l1));
    *reinterpret_cast<uint32_t*>(smem + off_hi) = *reinterpret_cast<uint32_t*>(&hp);
    *reinterpret_cast<uint32_t*>(smem + off_lo) = *reinterpret_cast<uint32_t*>(&lp);
}

__device__ __forceinline__ float2 unsplit_u32(uint32_t hi, uint32_t lo) {
    __nv_bfloat162 h = *reinterpret_cast<__nv_bfloat162*>(&hi);
    __nv_bfloat162 l = *reinterpret_cast<__nv_bfloat162*>(&lo);
    return make_float2(__low2float(h) + __low2float(l),
                       __high2float(h) + __high2float(l));
}

// ---------------- prep: split + reorder weights into chunked layout ----------------
__global__ void prep_kernel(const float* __restrict__ lw, const float* __restrict__ ew) {
    const int PER_CH = 80 * LDA;                 // 13440 elems per plane-chunk
    const int TOT_L  = NCHUNK * PER_CH;          // indexes (ch, r, c) over hi plane
    const int TOT_E  = 10 * PER_CH;
    for (int i = blockIdx.x * blockDim.x + threadIdx.x; i < TOT_L + TOT_E;
         i += gridDim.x * blockDim.x) {
        if (i < TOT_L) {
            int ch = i / PER_CH;
            int rc = i - ch * PER_CH;
            int r = rc / LDA, c = rc - r * LDA;
            int l = ch >> 1;
            int k = (ch & 1) * 80 + r;
            float v = (c < HIDDEN) ? lw[(size_t)l * HIDDEN * HIDDEN + k * HIDDEN + c] : 0.0f;
            __nv_bfloat16 hb = __float2bfloat16(v);
            __nv_bfloat16 lb = __float2bfloat16(v - __bfloat162float(hb));
            size_t base = (size_t)ch * (2 * PER_CH) + rc;
            g_lw[base] = hb;
            g_lw[base + PER_CH] = lb;
        } else {
            int j = i - TOT_L;
            int ch = j / PER_CH;
            int rc = j - ch * PER_CH;
            int r = rc / LDA, c = rc - r * LDA;
            int k = ch * 80 + r;
            float v = (k < IN_DIM && c < HIDDEN) ? ew[(size_t)k * HIDDEN + c] : 0.0f;
            __nv_bfloat16 hb = __float2bfloat16(v);
            __nv_bfloat16 lb = __float2bfloat16(v - __bfloat162float(hb));
            size_t base = (size_t)ch * (2 * PER_CH) + rc;
            g_ew[base] = hb;
            g_ew[base + PER_CH] = lb;
        }
    }
}

// ---------------- main kernel ----------------
__global__ void __launch_bounds__(NTH, 1)
resmlp_kernel(const float* __restrict__ x,  const float* __restrict__ eb,
              const float* __restrict__ hw, const float* __restrict__ hbias,
              float* __restrict__ out) {
    extern __shared__ char smem[];
    const uint32_t sb = smem_u32(smem);
    const int tid  = threadIdx.x;
    const int lane = tid & 31;
    const int w    = tid >> 5;
    const int cta  = blockIdx.x;

    const int a_lane_off = (16 * w + (lane & 15)) * STRB + (lane >> 4) * 16;
    const int b4_off     = (lane & 15) * STRB + (lane >> 4) * 16;
    const int qr = lane >> 2;
    const int qc = (lane & 3) * 2;

    float acc[20][4];
#pragma unroll
    for (int t = 0; t < 20; t++)
#pragma unroll
        for (int i = 0; i < 4; i++) acc[t][i] = 0.0f;

    // ================= Embed: h = x @ ew + eb  (K padded to 800, 5 outer chunks) ======
    const float* xbase = x + (size_t)cta * BM * IN_DIM;
    const char* gew = reinterpret_cast<const char*>(g_ew);
    for (int c5 = 0; c5 < 5; c5++) {
        __syncthreads();   // A + W buffers free (prior chunk's compute done everywhere)
        // two W chunks -> WB0|WB1 (contiguous 107520B)
        {
            const char* src = gew + (size_t)c5 * (2 * WCHUNK);
            for (int j = tid * 16; j < 2 * WCHUNK; j += NTH * 16)
                cp16(sb + WB0 + j, src + j);
            CP_COMMIT();
        }
        // stage x chunk (160 k-cols) into A hi/lo
        for (int idx = tid; idx < BM * 80; idx += NTH) {
            int r = idx / 80, p = idx - r * 80;
            int k = c5 * 160 + 2 * p;
            float2 v;
            if (k < IN_DIM) v = *reinterpret_cast<const float2*>(xbase + (size_t)r * IN_DIM + k);
            else            v = make_float2(0.0f, 0.0f);
            int off = r * STRB + p * 4;
            split_store(smem, A_HI + off, A_LO + off, v.x, v.y);
        }
        CP_WAIT(0);
        __syncthreads();
#pragma unroll
        for (int ks = 0; ks < 10; ks++) {
            uint32_t ah4[4], al4[4];
            ldsm_x4(ah4, sb + A_HI + a_lane_off + ks * 32);
            ldsm_x4(al4, sb + A_LO + a_lane_off + ks * 32);
            const uint32_t wrow = sb + WB0 + (ks / 5) * WCHUNK + b4_off + (ks % 5) * (16 * STRB);
#pragma unroll
            for (int tt = 0; tt < 10; tt++) {
                uint32_t bh[4], bl[4];
                ldsm_x4t(bh, wrow + tt * 32);
                ldsm_x4t(bl, wrow + WCH_PLANE + tt * 32);
                mma_bf16(acc[2 * tt],     ah4, bh[0], bh[1]);
                mma_bf16(acc[2 * tt],     ah4, bl[0], bl[1]);
                mma_bf16(acc[2 * tt],     al4, bh[0], bh[1]);
                mma_bf16(acc[2 * tt + 1], ah4, bh[2], bh[3]);
                mma_bf16(acc[2 * tt + 1], ah4, bl[2], bl[3]);
                mma_bf16(acc[2 * tt + 1], al4, bh[2], bh[3]);
            }
        }
    }
    // h = acc + eb -> A planes (warp-private rows), zero acc
    {
        const int r0 = 16 * w + qr;
#pragma unroll
        for (int t = 0; t < 20; t++) {
            const int cc = 8 * t + qc;
            const float b0 = eb[cc], b1 = eb[cc + 1];
#pragma unroll
            for (int hlf = 0; hlf < 2; hlf++) {
                int off = (r0 + 8 * hlf) * STRB + cc * 2;
                split_store(smem, A_HI + off, A_LO + off,
                            acc[t][2 * hlf] + b0, acc[t][2 * hlf + 1] + b1);
                acc[t][2 * hlf] = 0.0f; acc[t][2 * hlf + 1] = 0.0f;
            }
        }
    }
    __syncthreads();   // h visible; embed W region free

    // ================= 32 layers as 64 half-layer chunks, depth-1 prefetch =============
    const char* glw = reinterpret_cast<const char*>(g_lw);
    for (int j = tid * 16; j < WCHUNK; j += NTH * 16)   // prologue: chunk 0 -> WB0
        cp16(sb + WB0 + j, glw + j);
    CP_COMMIT();

    for (int ch = 0; ch < NCHUNK; ch++) {
        const uint32_t wb = (ch & 1) ? WB1 : WB0;
        CP_WAIT(0);
        __syncthreads();   // chunk ch visible; all warps done reading the other buffer
        if (ch + 1 < NCHUNK) {
            const uint32_t nb = (ch & 1) ? WB0 : WB1;
            const char* src = glw + (size_t)(ch + 1) * WCHUNK;
            for (int j = tid * 16; j < WCHUNK; j += NTH * 16)
                cp16(sb + nb + j, src + j);
            CP_COMMIT();
        }
        const int ksbase = (ch & 1) * 5;
#pragma unroll
        for (int j = 0; j < 5; j++) {
            const int ks = ksbase + j;
            uint32_t ah4[4], al4[4];
            ldsm_x4(ah4, sb + A_HI + a_lane_off + ks * 32);
            ldsm_x4(al4, sb + A_LO + a_lane_off + ks * 32);
            const uint32_t wrow = sb + wb + b4_off + j * (16 * STRB);
#pragma unroll
            for (int tt = 0; tt < 10; tt++) {
                uint32_t bh[4], bl[4];
                ldsm_x4t(bh, wrow + tt * 32);
                ldsm_x4t(bl, wrow + WCH_PLANE + tt * 32);
                mma_bf16(acc[2 * tt],     ah4, bh[0], bh[1]);
                mma_bf16(acc[2 * tt],     ah4, bl[0], bl[1]);
                mma_bf16(acc[2 * tt],     al4, bh[0], bh[1]);
                mma_bf16(acc[2 * tt + 1], ah4, bh[2], bh[3]);
                mma_bf16(acc[2 * tt + 1], ah4, bl[2], bl[3]);
                mma_bf16(acc[2 * tt + 1], al4, bh[2], bh[3]);
            }
        }
        if (ch & 1) {
            // end of layer: h = relu(acc) + h_old  (warp-private rows; next ldsm of A
            // is separated from these writes by the top-of-chunk __syncthreads)
            const int r0 = 16 * w + qr;
#pragma unroll
            for (int t = 0; t < 20; t++) {
                const int cb = (8 * t + qc) * 2;
#pragma unroll
                for (int hlf = 0; hlf < 2; hlf++) {
                    int off = (r0 + 8 * hlf) * STRB + cb;
                    uint32_t hpv = *reinterpret_cast<uint32_t*>(smem + A_HI + off);
                    uint32_t lpv = *reinterpret_cast<uint32_t*>(smem + A_LO + off);
                    float2 ho = unsplit_u32(hpv, lpv);
                    float n0 = fmaxf(acc[t][2 * hlf + 0], 0.0f) + ho.x;
                    float n1 = fmaxf(acc[t][2 * hlf + 1], 0.0f) + ho.y;
                    split_store(smem, A_HI + off, A_LO + off, n0, n1);
                    acc[t][2 * hlf] = 0.0f; acc[t][2 * hlf + 1] = 0.0f;
                }
            }
        }
    }

    // ================= Head: out = h @ head_w + head_b =================
    __syncthreads();
    float* hwS = reinterpret_cast<float*>(smem + WB0);
    for (int idx = tid; idx < HIDDEN * NCLASSES; idx += NTH) hwS[idx] = hw[idx];
    __syncthreads();
    if (tid < BM) {
        float a[NCLASSES];
#pragma unroll
        for (int cc = 0; cc < NCLASSES; cc++) a[cc] = hbias[cc];
        for (int k = 0; k < HIDDEN; k++) {
            int off = tid * STRB + k * 2;
            float hv = __bfloat162float(*reinterpret_cast<__nv_bfloat16*>(smem + A_HI + off))
                     + __bfloat162float(*reinterpret_cast<__nv_bfloat16*>(smem + A_LO + off));
#pragma unroll
            for (int cc = 0; cc < NCLASSES; cc++)
                a[cc] = fmaf(hv, hwS[k * NCLASSES + cc], a[cc]);
        }
        const size_t grow = (size_t)cta * BM + tid;
#pragma unroll
        for (int cc = 0; cc < NCLASSES; cc++) out[grow * NCLASSES + cc] = a[cc];
    }
}

extern "C" void kernel_launch(void* const* d_in, const int* in_sizes, int n_in,
                              void* d_out, int out_size) {
    const float* x  = (const float*)d_in[0];
    const float* ew = (const float*)d_in[1];
    const float* eb = (const float*)d_in[2];
    const float* lw = (const float*)d_in[3];
    const float* hw = (const float*)d_in[4];
    const float* hb = (const float*)d_in[5];
    float* out = (float*)d_out;

    const int B = in_sizes[0] / IN_DIM;   // 65536
    const int blocks = B / BM;            // 512

    prep_kernel<<<512, 256>>>(lw, ew);

    cudaFuncSetAttribute(resmlp_kernel,
                         cudaFuncAttributeMaxDynamicSharedMemorySize, SM_TOTAL);
    resmlp_kernel<<<blocks, NTH, SM_TOTAL>>>(x, eb, hw, hb, out);
}

// round 16
// speedup vs baseline: 1.0097x; 1.0097x over previous
#include <cuda_runtime.h>
#include <cuda_bf16.h>
#include <cstdint>

#define HIDDEN   160
#define IN_DIM   784
#define NLAYERS  32
#define NCLASSES 10
#define BM       128
#define NTH      256
#define LDA      168              // padded row length (bf16), 336B stride
#define STRB     (LDA * 2)

// W half-layer chunk: 80 k-rows x 168 cols, hi plane then lo plane
#define WCH_PLANE  26880          // 80*168*2 bytes
#define WCHUNK     53760          // hi+lo
#define NCHUNK     (NLAYERS * 2)  // 64

// SMEM layout
#define A_HI   0
#define A_LO   43008              // 128*336
#define WB0    86016
#define WB1    139776             // WB0 + WCHUNK (contiguous pair)
#define SM_TOTAL 193536

// pre-split weights, chunk-ordered
__device__ __align__(16) __nv_bfloat16 g_lw[NCHUNK * 2 * 80 * LDA];
__device__ __align__(16) __nv_bfloat16 g_ew[10 * 2 * 80 * LDA];

__device__ __forceinline__ uint32_t smem_u32(const void* p) {
    uint32_t a;
    asm("{ .reg .u64 t; cvta.to.shared.u64 t, %1; cvt.u32.u64 %0, t; }"
        : "=r"(a) : "l"(p));
    return a;
}

__device__ __forceinline__ void ldsm_x4(uint32_t (&r)[4], uint32_t addr) {
    asm volatile("ldmatrix.sync.aligned.m8n8.x4.shared.b16 {%0,%1,%2,%3}, [%4];"
        : "=r"(r[0]), "=r"(r[1]), "=r"(r[2]), "=r"(r[3]) : "r"(addr));
}

__device__ __forceinline__ void ldsm_x4t(uint32_t (&r)[4], uint32_t addr) {
    asm volatile("ldmatrix.sync.aligned.m8n8.x4.trans.shared.b16 {%0,%1,%2,%3}, [%4];"
        : "=r"(r[0]), "=r"(r[1]), "=r"(r[2]), "=r"(r[3]) : "r"(addr));
}

__device__ __forceinline__ void mma_bf16(float (&d)[4], const uint32_t* a,
                                         uint32_t b0, uint32_t b1) {
    asm volatile(
        "mma.sync.aligned.m16n8k16.row.col.f32.bf16.bf16.f32 "
        "{%0,%1,%2,%3}, {%4,%5,%6,%7}, {%8,%9}, {%0,%1,%2,%3};"
        : "+f"(d[0]), "+f"(d[1]), "+f"(d[2]), "+f"(d[3])
        : "r"(a[0]), "r"(a[1]), "r"(a[2]), "r"(a[3]), "r"(b0), "r"(b1));
}

__device__ __forceinline__ void cp16(uint32_t dst, const void* src) {
    asm volatile("cp.async.cg.shared.global [%0], [%1], 16;"
                 :: "r"(dst), "l"(src) : "memory");
}
#define CP_COMMIT() asm volatile("cp.async.commit_group;" ::: "memory")
#define CP_WAIT(n)  asm volatile("cp.async.wait_group %0;" :: "n"(n) : "memory")

__device__ __forceinline__ void split_store(char* smem, int off_hi, int off_lo,
                                            float v0, float v1) {
    __nv_bfloat16 h0 = __float2bfloat16(v0);
    __nv_bfloat16 h1 = __float2bfloat16(v1);
    float l0 = v0 - __bfloat162float(h0);
    float l1 = v1 - __bfloat162float(h1);
    __nv_bfloat162 hp = __halves2bfloat162(h0, h1);
    __nv_bfloat162 lp = __halves2bfloat162(__float2bfloat16(l0), __float2bfloat16(l1));
    *reinterpret_cast<uint32_t*>(smem + off_hi) = *reinterpret_cast<uint32_t*>(&hp);
    *reinterpret_cast<uint32_t*>(smem + off_lo) = *reinterpret_cast<uint32_t*>(&lp);
}

__device__ __forceinline__ float2 unsplit_u32(uint32_t hi, uint32_t lo) {
    __nv_bfloat162 h = *reinterpret_cast<__nv_bfloat162*>(&hi);
    __nv_bfloat162 l = *reinterpret_cast<__nv_bfloat162*>(&lo);
    return make_float2(__low2float(h) + __low2float(l),
                       __high2float(h) + __high2float(l));
}

// ---------------- prep: split + reorder weights into chunked layout ----------------
__global__ void prep_kernel(const float* __restrict__ lw, const float* __restrict__ ew) {
    const int PER_CH = 80 * LDA;
    const int TOT_L  = NCHUNK * PER_CH;
    const int TOT_E  = 10 * PER_CH;
    for (int i = blockIdx.x * blockDim.x + threadIdx.x; i < TOT_L + TOT_E;
         i += gridDim.x * blockDim.x) {
        if (i < TOT_L) {
            int ch = i / PER_CH;
            int rc = i - ch * PER_CH;
            int r = rc / LDA, c = rc - r * LDA;
            int l = ch >> 1;
            int k = (ch & 1) * 80 + r;
            float v = (c < HIDDEN) ? lw[(size_t)l * HIDDEN * HIDDEN + k * HIDDEN + c] : 0.0f;
            __nv_bfloat16 hb = __float2bfloat16(v);
            __nv_bfloat16 lb = __float2bfloat16(v - __bfloat162float(hb));
            size_t base = (size_t)ch * (2 * PER_CH) + rc;
            g_lw[base] = hb;
            g_lw[base + PER_CH] = lb;
        } else {
            int j = i - TOT_L;
            int ch = j / PER_CH;
            int rc = j - ch * PER_CH;
            int r = rc / LDA, c = rc - r * LDA;
            int k = ch * 80 + r;
            float v = (k < IN_DIM && c < HIDDEN) ? ew[(size_t)k * HIDDEN + c] : 0.0f;
            __nv_bfloat16 hb = __float2bfloat16(v);
            __nv_bfloat16 lb = __float2bfloat16(v - __bfloat162float(hb));
            size_t base = (size_t)ch * (2 * PER_CH) + rc;
            g_ew[base] = hb;
            g_ew[base + PER_CH] = lb;
        }
    }
}

// ---------------- main kernel ----------------
__global__ void __launch_bounds__(NTH, 1)
resmlp_kernel(const float* __restrict__ x,  const float* __restrict__ eb,
              const float* __restrict__ hw, const float* __restrict__ hbias,
              float* __restrict__ out) {
    extern __shared__ char smem[];
    const uint32_t sb = smem_u32(smem);
    const int tid  = threadIdx.x;
    const int lane = tid & 31;
    const int w    = tid >> 5;
    const int cta  = blockIdx.x;

    // warp tiling: wm = row-group (32 rows each), wn = N half (80 cols each)
    const int wm = w & 3;
    const int wn = w >> 2;

    // ldmatrix lane offsets
    const int aoff0 = (32 * wm + (lane & 15)) * STRB + (lane >> 4) * 16;   // rows rg=0
    const int aoff1 = aoff0 + 16 * STRB;                                   // rows rg=1
    const int b4_off = (lane & 15) * STRB + (lane >> 4) * 16 + wn * 160;   // W cols base

    const int qr = lane >> 2;
    const int qc = (lane & 3) * 2;

    float acc[2][10][4];
#pragma unroll
    for (int rg = 0; rg < 2; rg++)
#pragma unroll
        for (int t = 0; t < 10; t++)
#pragma unroll
            for (int i = 0; i < 4; i++) acc[rg][t][i] = 0.0f;

    // ================= Embed: h = x @ ew + eb  (K padded to 800, 5 outer chunks) ======
    const float* xbase = x + (size_t)cta * BM * IN_DIM;
    const char* gew = reinterpret_cast<const char*>(g_ew);
    for (int c5 = 0; c5 < 5; c5++) {
        __syncthreads();
        {
            const char* src = gew + (size_t)c5 * (2 * WCHUNK);
            for (int j = tid * 16; j < 2 * WCHUNK; j += NTH * 16)
                cp16(sb + WB0 + j, src + j);
            CP_COMMIT();
        }
        for (int idx = tid; idx < BM * 80; idx += NTH) {
            int r = idx / 80, p = idx - r * 80;
            int k = c5 * 160 + 2 * p;
            float2 v;
            if (k < IN_DIM) v = *reinterpret_cast<const float2*>(xbase + (size_t)r * IN_DIM + k);
            else            v = make_float2(0.0f, 0.0f);
            int off = r * STRB + p * 4;
            split_store(smem, A_HI + off, A_LO + off, v.x, v.y);
        }
        CP_WAIT(0);
        __syncthreads();
#pragma unroll
        for (int ks = 0; ks < 10; ks++) {
            uint32_t ah[2][4], al[2][4];
            ldsm_x4(ah[0], sb + A_HI + aoff0 + ks * 32);
            ldsm_x4(al[0], sb + A_LO + aoff0 + ks * 32);
            ldsm_x4(ah[1], sb + A_HI + aoff1 + ks * 32);
            ldsm_x4(al[1], sb + A_LO + aoff1 + ks * 32);
            const uint32_t wrow = sb + WB0 + (ks / 5) * WCHUNK + b4_off + (ks % 5) * (16 * STRB);
#pragma unroll
            for (int t = 0; t < 5; t++) {
                uint32_t bh[4], bl[4];
                ldsm_x4t(bh, wrow + t * 32);
                ldsm_x4t(bl, wrow + WCH_PLANE + t * 32);
#pragma unroll
                for (int rg = 0; rg < 2; rg++) {
                    mma_bf16(acc[rg][2 * t],     ah[rg], bh[0], bh[1]);
                    mma_bf16(acc[rg][2 * t],     ah[rg], bl[0], bl[1]);
                    mma_bf16(acc[rg][2 * t],     al[rg], bh[0], bh[1]);
                    mma_bf16(acc[rg][2 * t + 1], ah[rg], bh[2], bh[3]);
                    mma_bf16(acc[rg][2 * t + 1], ah[rg], bl[2], bl[3]);
                    mma_bf16(acc[rg][2 * t + 1], al[rg], bh[2], bh[3]);
                }
            }
        }
    }
    // RACE FIX: partner warp (same rows, other N-half) may still be reading A (x);
    // barrier before overwriting A planes with h.
    __syncthreads();
    // h = acc + eb -> A planes (warp-disjoint 32x80 region), zero acc
#pragma unroll
    for (int rg = 0; rg < 2; rg++) {
        const int r0 = 32 * wm + 16 * rg + qr;
#pragma unroll
        for (int t = 0; t < 10; t++) {
            const int cc = wn * 80 + 8 * t + qc;
            const float b0 = eb[cc], b1 = eb[cc + 1];
#pragma unroll
            for (int hlf = 0; hlf < 2; hlf++) {
                int off = (r0 + 8 * hlf) * STRB + cc * 2;
                split_store(smem, A_HI + off, A_LO + off,
                            acc[rg][t][2 * hlf] + b0, acc[rg][t][2 * hlf + 1] + b1);
                acc[rg][t][2 * hlf] = 0.0f; acc[rg][t][2 * hlf + 1] = 0.0f;
            }
        }
    }
    __syncthreads();

    // ================= 32 layers as 64 half-layer chunks, depth-1 prefetch =============
    const char* glw = reinterpret_cast<const char*>(g_lw);
    for (int j = tid * 16; j < WCHUNK; j += NTH * 16)
        cp16(sb + WB0 + j, glw + j);
    CP_COMMIT();

    for (int ch = 0; ch < NCHUNK; ch++) {
        const uint32_t wb = (ch & 1) ? WB1 : WB0;
        CP_WAIT(0);
        __syncthreads();
        if (ch + 1 < NCHUNK) {
            const uint32_t nb = (ch & 1) ? WB0 : WB1;
            const char* src = glw + (size_t)(ch + 1) * WCHUNK;
            for (int j = tid * 16; j < WCHUNK; j += NTH * 16)
                cp16(sb + nb + j, src + j);
            CP_COMMIT();
        }
        const int ksbase = (ch & 1) * 5;
#pragma unroll
        for (int j = 0; j < 5; j++) {
            const int ks = ksbase + j;
            uint32_t ah[2][4], al[2][4];
            ldsm_x4(ah[0], sb + A_HI + aoff0 + ks * 32);
            ldsm_x4(al[0], sb + A_LO + aoff0 + ks * 32);
            ldsm_x4(ah[1], sb + A_HI + aoff1 + ks * 32);
            ldsm_x4(al[1], sb + A_LO + aoff1 + ks * 32);
            const uint32_t wrow = sb + wb + b4_off + j * (16 * STRB);
#pragma unroll
            for (int t = 0; t < 5; t++) {
                uint32_t bh[4], bl[4];
                ldsm_x4t(bh, wrow + t * 32);
                ldsm_x4t(bl, wrow + WCH_PLANE + t * 32);
#pragma unroll
                for (int rg = 0; rg < 2; rg++) {
                    mma_bf16(acc[rg][2 * t],     ah[rg], bh[0], bh[1]);
                    mma_bf16(acc[rg][2 * t],     ah[rg], bl[0], bl[1]);
                    mma_bf16(acc[rg][2 * t],     al[rg], bh[0], bh[1]);
                    mma_bf16(acc[rg][2 * t + 1], ah[rg], bh[2], bh[3]);
                    mma_bf16(acc[rg][2 * t + 1], ah[rg], bl[2], bl[3]);
                    mma_bf16(acc[rg][2 * t + 1], al[rg], bh[2], bh[3]);
                }
            }
        }
        if (ch & 1) {
            // RACE FIX: partner warp (same rows, other N-half) may still be doing
            // its ldmatrix A reads of the cols this warp is about to overwrite.
            // Barrier before the h update.
            __syncthreads();
            // end of layer: h = relu(acc) + h_old on this warp's 32x80 region.
#pragma unroll
            for (int rg = 0; rg < 2; rg++) {
                const int r0 = 32 * wm + 16 * rg + qr;
#pragma unroll
                for (int t = 0; t < 10; t++) {
                    const int cb = (wn * 80 + 8 * t + qc) * 2;
#pragma unroll
                    for (int hlf = 0; hlf < 2; hlf++) {
                        int off = (r0 + 8 * hlf) * STRB + cb;
                        uint32_t hpv = *reinterpret_cast<uint32_t*>(smem + A_HI + off);
                        uint32_t lpv = *reinterpret_cast<uint32_t*>(smem + A_LO + off);
                        float2 ho = unsplit_u32(hpv, lpv);
                        float n0 = fmaxf(acc[rg][t][2 * hlf + 0], 0.0f) + ho.x;
                        float n1 = fmaxf(acc[rg][t][2 * hlf + 1], 0.0f) + ho.y;
                        split_store(smem, A_HI + off, A_LO + off, n0, n1);
                        acc[rg][t][2 * hlf] = 0.0f; acc[rg][t][2 * hlf + 1] = 0.0f;
                    }
                }
            }
        }
    }

    // ================= Head: out = h @ head_w + head_b =================
    __syncthreads();
    float* hwS = reinterpret_cast<float*>(smem + WB0);
    for (int idx = tid; idx < HIDDEN * NCLASSES; idx += NTH) hwS[idx] = hw[idx];
    __syncthreads();
    if (tid < BM) {
        float a[NCLASSES];
#pragma unroll
        for (int cc = 0; cc < NCLASSES; cc++) a[cc] = hbias[cc];
        for (int k = 0; k < HIDDEN; k++) {
            int off = tid * STRB + k * 2;
            float hv = __bfloat162float(*reinterpret_cast<__nv_bfloat16*>(smem + A_HI + off))
                     + __bfloat162float(*reinterpret_cast<__nv_bfloat16*>(smem + A_LO + off));
#pragma unroll
            for (int cc = 0; cc < NCLASSES; cc++)
                a[cc] = fmaf(hv, hwS[k * NCLASSES + cc], a[cc]);
        }
        const size_t grow = (size_t)cta * BM + tid;
#pragma unroll
        for (int cc = 0; cc < NCLASSES; cc++) out[grow * NCLASSES + cc] = a[cc];
    }
}

extern "C" void kernel_launch(void* const* d_in, const int* in_sizes, int n_in,
                              void* d_out, int out_size) {
    const float* x  = (const float*)d_in[0];
    const float* ew = (const float*)d_in[1];
    const float* eb = (const float*)d_in[2];
    const float* lw = (const float*)d_in[3];
    const float* hw = (const float*)d_in[4];
    const float* hb = (const float*)d_in[5];
    float* out = (float*)d_out;

    const int B = in_sizes[0] / IN_DIM;   // 65536
    const int blocks = B / BM;            // 512

    prep_kernel<<<512, 256>>>(lw, ew);

    cudaFuncSetAttribute(resmlp_kernel,
                         cudaFuncAttributeMaxDynamicSharedMemorySize, SM_TOTAL);
    resmlp_kernel<<<blocks, NTH, SM_TOTAL>>>(x, eb, hw, hb, out);
}